// round 17
// baseline (speedup 1.0000x reference)
#include <cuda_runtime.h>
#include <cuda_bf16.h>
#include <mma.h>
#include <math.h>

// GRU: B=128, T=512, I=256, H=512. out = final h [1,128,512] fp32.
// Warp-specialized persistent kernel, 128 CTAs (4 batch x 32 j).
// Pre-phase: x@W_ih^T for all t -> g_xg (fp32, bias folded).
// Main loop: 2 phases per timestep (one per batch half, 1 syncthreads each).
//   warps 0-11 : h-projection mma (wmma bf16 hi/lo 3-product, 3 accumulators)
//   warps 12-15: gates -> publish flag -> poll peers -> stage h (other half)
// Producer-flag sync (32-CTA groups), h carried in service registers.

using namespace nvcuda;

#define BATCH 128
#define TT    512
#define II    256
#define HH    512
#define GB    4
#define GJ    32
#define BC    32
#define JC    16
#define NCTA  128
#define NTHR  512

#define WHHS 520      // u16 per W_hh row (512+8)
#define USTR 520      // u16 per U row (512+8)
#define XSTR 264      // u16 per x-stage row (256+8)
#define WIHS 264      // u16 per W_ih row

// SMEM byte offsets
#define SM_WHH_H 0                      // 48*520*2 = 49920
#define SM_WHH_L 49920                  // -> 99840
#define SM_U0H   99840                  // half A h hi  16*520*2 = 16640
#define SM_U0L   116480
#define SM_U1H   133120                 // half B
#define SM_U1L   149760                 // -> 166400
#define SM_DRED  166400                 // 24 tiles * 1024 = 24576 -> 190976
#define SM_BS    190976                 // 96 f32 -> 191360
#define SM_XBH   191360                 // pre-phase x hi 32*264*2 = 16896
#define SM_XBL   208256                 // -> 225152
#define SMEM_BYTES 225280
// pre-phase W_ih overlay (dead before U planes are first used)
#define SM_WIH_H SM_U0H                 // 25344
#define SM_WIH_L SM_U1H                 // 25344

__device__ float          g_xg[(size_t)GJ*BATCH*TT*48];   // [gj][b][t][48]
__device__ unsigned short g_hsh[2][BATCH*HH];
__device__ unsigned short g_hsl[2][BATCH*HH];
__device__ __align__(128) unsigned int g_flags[GB*2][32];
__device__ unsigned int   g_count = 0;
__device__ unsigned int   g_phase = 0;

__device__ __forceinline__ float sigm(float x) {
    return 1.0f / (1.0f + __expf(-x));
}
__device__ __forceinline__ unsigned short bhi(float v) {
    return __bfloat16_as_ushort(__float2bfloat16(v));
}
__device__ __forceinline__ unsigned short blo(float v) {
    __nv_bfloat16 h = __float2bfloat16(v);
    return __bfloat16_as_ushort(__float2bfloat16(v - __bfloat162float(h)));
}
__device__ __forceinline__ void barx(int id) {
    asm volatile("bar.sync %0, %1;" :: "r"(id), "r"(128) : "memory");
}

extern "C" __global__ void __launch_bounds__(NTHR, 1)
gru_persistent_kernel(const float* __restrict__ x,      // [B, T, I]
                      const float* __restrict__ W_ih,   // [3H, I]
                      const float* __restrict__ W_hh,   // [3H, H]
                      const float* __restrict__ b_ih,   // [3H]
                      const float* __restrict__ b_hh,   // [3H]
                      float* __restrict__ out)          // [1, B, H]
{
    extern __shared__ char smem[];
    unsigned short* WhhH = (unsigned short*)(smem + SM_WHH_H);
    unsigned short* WhhL = (unsigned short*)(smem + SM_WHH_L);
    unsigned short* UH[2] = {(unsigned short*)(smem + SM_U0H),
                             (unsigned short*)(smem + SM_U1H)};
    unsigned short* UL[2] = {(unsigned short*)(smem + SM_U0L),
                             (unsigned short*)(smem + SM_U1L)};
    unsigned short* WihH = (unsigned short*)(smem + SM_WIH_H);
    unsigned short* WihL = (unsigned short*)(smem + SM_WIH_L);
    unsigned short* XBH  = (unsigned short*)(smem + SM_XBH);
    unsigned short* XBL  = (unsigned short*)(smem + SM_XBL);
    float* DredF = (float*)(smem + SM_DRED);
    float* B_s   = (float*)(smem + SM_BS);

    const int tid = threadIdx.x;
    const int bx  = blockIdx.x;
    const int gb  = bx & (GB - 1);
    const int gj  = bx >> 2;
    const int b0  = gb * BC;
    const int j0  = gj * JC;

    unsigned base = 0;
    if (tid == 0) base = *((volatile unsigned*)&g_phase);

    // ---- one-time: W_hh hi/lo, W_ih hi/lo (overlay), biases ----
    for (int idx = tid; idx < 48 * 512; idx += NTHR) {
        int row = idx >> 9, col = idx & 511;
        int G = (row < 16) ? j0 + row
              : (row < 32) ? 512 + j0 + (row - 16)
                           : 1024 + j0 + (row - 32);
        float v = W_hh[G * HH + col];
        WhhH[row * WHHS + col] = bhi(v);
        WhhL[row * WHHS + col] = blo(v);
    }
    for (int idx = tid; idx < 48 * 256; idx += NTHR) {
        int row = idx >> 8, col = idx & 255;
        int G = (row < 16) ? j0 + row
              : (row < 32) ? 512 + j0 + (row - 16)
                           : 1024 + j0 + (row - 32);
        float v = W_ih[G * II + col];
        WihH[row * WIHS + col] = bhi(v);
        WihL[row * WIHS + col] = blo(v);
    }
    if (tid < 96) {
        int loc = tid % 48;
        int G = (loc < 16) ? j0 + loc
              : (loc < 32) ? 512 + j0 + (loc - 16)
                           : 1024 + j0 + (loc - 32);
        B_s[tid] = (tid < 48) ? b_hh[G] : b_ih[G];
    }
    __syncthreads();

    const int w = tid >> 5;

    wmma::fragment<wmma::matrix_a, 16, 16, 16, __nv_bfloat16, wmma::row_major> fa_h, fa_l;
    wmma::fragment<wmma::matrix_b, 16, 16, 16, __nv_bfloat16, wmma::col_major> fb_h, fb_l;
    wmma::fragment<wmma::accumulator, 16, 16, 16, float> accA, accB, accC;

    // ================= pre-phase: g_xg = x @ W_ih^T + b_ih =================
    {
        const int srow = tid >> 4;          // 0..31
        const int sk16 = (tid & 15) * 16;
        const int jjP  = tid & 15;
        const int bbP  = tid >> 4;          // 0..31
        const int btl  = bbP >> 4;
        const int locP = (bbP & 15) * 16 + jjP;
        const size_t xg_cta = (((size_t)gj * BATCH + b0 + bbP) * TT) * 48;

        const int kh    = w & 1;
        const int tau   = w >> 1;
        const int btileP = tau / 3;
        const int ntileP = tau % 3;

        auto stage_x = [&](int t) {
            const float* xs = x + ((size_t)(b0 + srow) * TT + t) * II + sk16;
            float vv[16];
            *(float4*)(vv + 0)  = *(const float4*)(xs + 0);
            *(float4*)(vv + 4)  = *(const float4*)(xs + 4);
            *(float4*)(vv + 8)  = *(const float4*)(xs + 8);
            *(float4*)(vv + 12) = *(const float4*)(xs + 12);
            unsigned hp[8], lp[8];
            #pragma unroll
            for (int k2 = 0; k2 < 8; k2++) {
                unsigned h0 = bhi(vv[2*k2]), h1 = bhi(vv[2*k2+1]);
                unsigned l0 = blo(vv[2*k2]), l1 = blo(vv[2*k2+1]);
                hp[k2] = h0 | (h1 << 16);
                lp[k2] = l0 | (l1 << 16);
            }
            uint4* dh = (uint4*)(XBH + srow * XSTR + sk16);
            uint4* dl = (uint4*)(XBL + srow * XSTR + sk16);
            dh[0] = make_uint4(hp[0], hp[1], hp[2], hp[3]);
            dh[1] = make_uint4(hp[4], hp[5], hp[6], hp[7]);
            dl[0] = make_uint4(lp[0], lp[1], lp[2], lp[3]);
            dl[1] = make_uint4(lp[4], lp[5], lp[6], lp[7]);
        };

        stage_x(0);
        __syncthreads();
        for (int t = 0; t < TT; t++) {
            if (w < 12) {
                wmma::fill_fragment(accA, 0.0f);
                wmma::fill_fragment(accB, 0.0f);
                wmma::fill_fragment(accC, 0.0f);
                const __nv_bfloat16* Ah = (const __nv_bfloat16*)(XBH + btileP * 16 * XSTR);
                const __nv_bfloat16* Al = (const __nv_bfloat16*)(XBL + btileP * 16 * XSTR);
                const __nv_bfloat16* Bh = (const __nv_bfloat16*)(WihH + ntileP * 16 * WIHS);
                const __nv_bfloat16* Bl = (const __nv_bfloat16*)(WihL + ntileP * 16 * WIHS);
                #pragma unroll
                for (int i = 0; i < 8; i++) {
                    int ks = kh * 8 + i;
                    wmma::load_matrix_sync(fa_h, Ah + ks * 16, XSTR);
                    wmma::load_matrix_sync(fa_l, Al + ks * 16, XSTR);
                    wmma::load_matrix_sync(fb_h, Bh + ks * 16, WIHS);
                    wmma::load_matrix_sync(fb_l, Bl + ks * 16, WIHS);
                    wmma::mma_sync(accA, fa_h, fb_h, accA);
                    wmma::mma_sync(accB, fa_h, fb_l, accB);
                    wmma::mma_sync(accC, fa_l, fb_h, accC);
                }
                #pragma unroll
                for (int i = 0; i < accA.num_elements; i++)
                    accA.x[i] += accB.x[i] + accC.x[i];
                wmma::store_matrix_sync(
                    DredF + ((t & 1) * 12 + (btileP * 3 + ntileP) * 2 + kh) * 256,
                    accA, 16, wmma::mem_row_major);
            }
            __syncthreads();
            {
                const float* Dp = DredF + (t & 1) * 12 * 256;
                const size_t xb = xg_cta + (size_t)t * 48;
                #pragma unroll
                for (int g = 0; g < 3; g++) {
                    float v = Dp[((btl * 3 + g) * 2 + 0) * 256 + locP]
                            + Dp[((btl * 3 + g) * 2 + 1) * 256 + locP]
                            + B_s[48 + g * 16 + jjP];
                    g_xg[xb + g * 16 + jjP] = v;
                }
                if (t + 1 < TT) stage_x(t + 1);
            }
            __syncthreads();
        }
    }

    // ---- zero U planes (h(-1)=0 for both halves); reset flags ----
    {
        unsigned* uz = (unsigned*)(smem + SM_U0H);
        for (int i = tid; i < 4 * 16 * USTR / 2; i += NTHR) uz[i] = 0u;
        if (tid == 0) {
            *((volatile unsigned*)&g_flags[gb * 2 + 0][gj]) = 0u;
            *((volatile unsigned*)&g_flags[gb * 2 + 1][gj]) = 0u;
        }
    }
    __syncthreads();
    // init barrier (global, self-cleaning)
    if (tid == 0) {
        __threadfence();
        if (atomicAdd(&g_count, 1u) == NCTA - 1u) {
            g_count = 0;
            __threadfence();
            *((volatile unsigned*)&g_phase) = base + 1u;
        }
        while ((unsigned)(*((volatile unsigned*)&g_phase) - base) < 1u) {
            __nanosleep(32);
        }
        __threadfence();
    }
    __syncthreads();

    // ================= main loop: warp-specialized phases =================
    const int ntileC = (w < 12) ? (w >> 2) : 0;   // 0..2
    const int kslC   = w & 3;

    // service thread state (warps 12-15)
    const int s_tid = tid - 384;                  // 0..127 when valid
    const int e0    = s_tid * 2;
    const int row_e[2] = { (e0 >> 4) & 15, ((e0 + 1) >> 4) & 15 };
    const int jj_e [2] = { e0 & 15, (e0 + 1) & 15 };
    const int hrow  = s_tid >> 3;                 // 0..15 staging row
    const int hseg  = (s_tid & 7) * 64;           // u16 col base
    float hold[2][2] = {{0.0f, 0.0f}, {0.0f, 0.0f}};
    float pf_r[2], pf_z[2], pf_n[2];

    auto prefetch_xg = [&](int hn, int tn) {
        #pragma unroll
        for (int e = 0; e < 2; e++) {
            const size_t xb = (((size_t)gj * BATCH + b0 + hn * 16 + row_e[e]) * TT + tn) * 48;
            pf_r[e] = g_xg[xb + jj_e[e]];
            pf_z[e] = g_xg[xb + 16 + jj_e[e]];
            pf_n[e] = g_xg[xb + 32 + jj_e[e]];
        }
    };

    if (w >= 12) prefetch_xg(0, 0);   // for phase 1 gates (half A, t=0)

    for (int p = 0; p <= 2 * TT; p++) {
        if (w < 12) {
            if (p < 2 * TT) {
                const int hx = p & 1;
                wmma::fill_fragment(accA, 0.0f);
                wmma::fill_fragment(accB, 0.0f);
                wmma::fill_fragment(accC, 0.0f);
                const __nv_bfloat16* Ah = (const __nv_bfloat16*)UH[hx];
                const __nv_bfloat16* Al = (const __nv_bfloat16*)UL[hx];
                const __nv_bfloat16* Bh = (const __nv_bfloat16*)(WhhH + ntileC * 16 * WHHS);
                const __nv_bfloat16* Bl = (const __nv_bfloat16*)(WhhL + ntileC * 16 * WHHS);
                #pragma unroll
                for (int i = 0; i < 8; i++) {
                    const int ks = kslC * 8 + i;
                    wmma::load_matrix_sync(fa_h, Ah + ks * 16, USTR);
                    wmma::load_matrix_sync(fa_l, Al + ks * 16, USTR);
                    wmma::load_matrix_sync(fb_h, Bh + ks * 16, WHHS);
                    wmma::load_matrix_sync(fb_l, Bl + ks * 16, WHHS);
                    wmma::mma_sync(accA, fa_h, fb_h, accA);
                    wmma::mma_sync(accB, fa_h, fb_l, accB);
                    wmma::mma_sync(accC, fa_l, fb_h, accC);
                }
                #pragma unroll
                for (int i = 0; i < accA.num_elements; i++)
                    accA.x[i] += accB.x[i] + accC.x[i];
                wmma::store_matrix_sync(DredF + (hx * 12 + ntileC * 4 + kslC) * 256,
                                        accA, 16, wmma::mem_row_major);
            }
        } else if (p >= 1) {
            const int hq = (p & 1) ^ 1;
            const int tq = (p - 1) >> 1;
            const int par = tq & 1;

            // gates for half hq, time tq
            #pragma unroll
            for (int e = 0; e < 2; e++) {
                const int loc = row_e[e] * 16 + jj_e[e];
                float dr = 0.0f, dz = 0.0f, dn = 0.0f;
                #pragma unroll
                for (int s = 0; s < 4; s++) {
                    dr += DredF[(hq * 12 + 0 * 4 + s) * 256 + loc];
                    dz += DredF[(hq * 12 + 1 * 4 + s) * 256 + loc];
                    dn += DredF[(hq * 12 + 2 * 4 + s) * 256 + loc];
                }
                float r = sigm(pf_r[e] + dr + B_s[jj_e[e]]);
                float z = sigm(pf_z[e] + dz + B_s[16 + jj_e[e]]);
                float n = tanhf(pf_n[e] + r * (dn + B_s[32 + jj_e[e]]));
                float hv = n + z * (hold[hq][e] - n);
                hold[hq][e] = hv;
                const int gi = (b0 + hq * 16 + row_e[e]) * HH + j0 + jj_e[e];
                g_hsh[par][gi] = bhi(hv);
                g_hsl[par][gi] = blo(hv);
                if (tq == TT - 1) out[gi] = hv;
            }
            __threadfence();
            barx(1);
            if (s_tid == 0 && tq + 1 < TT)
                *((volatile unsigned*)&g_flags[gb * 2 + hq][gj]) = (unsigned)(tq + 1);

            // prefetch xg for next phase's gates (half = p&1, t = p>>1)
            if (p < 2 * TT) prefetch_xg(p & 1, p >> 1);

            if (tq + 1 < TT) {
                // poll peers' flags (warp 12), then stage h_hq(tq)
                if (s_tid < 32) {
                    const volatile unsigned* fl = &g_flags[gb * 2 + hq][0];
                    for (;;) {
                        unsigned v = fl[s_tid];
                        if (!__any_sync(0xFFFFFFFFu, v < (unsigned)(tq + 1))) break;
                        __nanosleep(32);
                    }
                    __threadfence();
                }
                barx(2);
                const int goff = (b0 + hq * 16 + hrow) * HH + hseg;
                const uint4* sh = (const uint4*)(g_hsh[par] + goff);
                const uint4* sl = (const uint4*)(g_hsl[par] + goff);
                uint4* dh = (uint4*)(UH[hq] + hrow * USTR + hseg);
                uint4* dl = (uint4*)(UL[hq] + hrow * USTR + hseg);
                #pragma unroll
                for (int i = 0; i < 8; i++) dh[i] = sh[i];
                #pragma unroll
                for (int i = 0; i < 8; i++) dl[i] = sl[i];
            }
        } else {
            // service warps, p == 0: nothing (prefetch done in prologue)
        }
        __syncthreads();
    }
}

extern "C" void kernel_launch(void* const* d_in, const int* in_sizes, int n_in,
                              void* d_out, int out_size) {
    (void)in_sizes; (void)n_in; (void)out_size;
    cudaFuncSetAttribute(gru_persistent_kernel,
                         cudaFuncAttributeMaxDynamicSharedMemorySize, SMEM_BYTES);
    gru_persistent_kernel<<<NCTA, NTHR, SMEM_BYTES>>>(
        (const float*)d_in[0],
        (const float*)d_in[1],
        (const float*)d_in[2],
        (const float*)d_in[3],
        (const float*)d_in[4],
        (float*)d_out);
}